// round 1
// baseline (speedup 1.0000x reference)
#include <cuda_runtime.h>

#define NB 2
#define NS 2048
#define NE 1024
#define NH 16
#define ND 64
#define SC 32       // s-chunks for pv partials
#define SCLEN 64    // s per chunk (SC*SCLEN == NS)

// Scratch (allocation-free: device globals)
__device__ float g_q[NB*NE];
__device__ float g_qwk[NB*NH*NE];        // [b][h][e]
__device__ float g_p[NB*NH*NS];          // scores -> softmax in place
__device__ float g_pvp[NB*SC*NH*NE];     // pv partials [b][sc][h][e]  (4 MB)
__device__ float g_pv[NB*NH*NE];
__device__ float g_o[NB*NE];
__device__ float g_y[NB*NE];

__device__ __forceinline__ float dot4(float4 a, float4 b){
  return fmaf(a.x,b.x, fmaf(a.y,b.y, fmaf(a.z,b.z, a.w*b.w)));
}
__device__ __forceinline__ float warp_sum(float v){
#pragma unroll
  for (int o=16;o>0;o>>=1) v += __shfl_xor_sync(0xffffffffu, v, o);
  return v;
}

// K1: g_q[b][j] = dot(inputs[b, S-1, :], Wq[j, :])   (warp per output)
__global__ void k_q(const float* __restrict__ inputs, const float* __restrict__ Wq){
  int gw = (blockIdx.x*blockDim.x + threadIdx.x) >> 5;
  int lane = threadIdx.x & 31;
  int b = gw >> 10, j = gw & 1023;
  const float4* xr = (const float4*)(inputs + ((size_t)b*NS + (NS-1))*NE);
  const float4* wr = (const float4*)(Wq + (size_t)j*NE);
  float acc = 0.f;
#pragma unroll
  for (int it=0; it<8; ++it) acc += dot4(xr[lane+it*32], wr[lane+it*32]);
  acc = warp_sum(acc);
  if (!lane) g_q[b*NE+j] = acc;
}

// K2: g_qwk[b][h][e] = sum_d g_q[b][h*64+d] * Wk[h*64+d][e]
__global__ void k_qwk(const float* __restrict__ Wk){
  int h = blockIdx.x, b = blockIdx.y;
  __shared__ float qs[ND];
  if (threadIdx.x < ND) qs[threadIdx.x] = g_q[b*NE + h*ND + threadIdx.x];
  __syncthreads();
  int e4 = threadIdx.x;              // 0..255 (float4 index)
  const float4* Wk4 = (const float4*)Wk;
  float4 acc = make_float4(0.f,0.f,0.f,0.f);
#pragma unroll 8
  for (int d=0; d<ND; ++d){
    float4 w = Wk4[(size_t)(h*ND + d)*256 + e4];
    float qv = qs[d];
    acc.x = fmaf(qv,w.x,acc.x); acc.y = fmaf(qv,w.y,acc.y);
    acc.z = fmaf(qv,w.z,acc.z); acc.w = fmaf(qv,w.w,acc.w);
  }
  ((float4*)g_qwk)[(size_t)(b*NH + h)*256 + e4] = acc;
}

// K3: scores[b][h][s] = dot(embK[b,s,:], qwk[b,h,:]); qwk cached in 64KB smem.
// Block: 256 thr = 8 warps; each warp does 4 s rows, all 16 heads.
__global__ void __launch_bounds__(256) k_scores(const float* __restrict__ embK){
  extern __shared__ float qwk_s[];     // [NH][NE] = 64 KB
  int b = blockIdx.y;
  {
    const float4* src = (const float4*)(g_qwk + (size_t)b*NH*NE);
    float4* dst = (float4*)qwk_s;
#pragma unroll
    for (int i=0;i<16;i++) dst[threadIdx.x + i*256] = src[threadIdx.x + i*256];
  }
  __syncthreads();
  int wid = threadIdx.x >> 5, lane = threadIdx.x & 31;
  int s = blockIdx.x*32 + wid*4;
  const float4* r = (const float4*)(embK + ((size_t)b*NS + s)*NE);
  float acc[NH][4];
#pragma unroll
  for (int h=0;h<NH;h++){
#pragma unroll
    for (int k=0;k<4;k++) acc[h][k]=0.f;
  }
#pragma unroll
  for (int it=0; it<8; ++it){
    int e4 = lane + it*32;
    float4 x0 = r[e4];
    float4 x1 = r[e4 + 256];
    float4 x2 = r[e4 + 512];
    float4 x3 = r[e4 + 768];
#pragma unroll
    for (int h=0; h<NH; ++h){
      float4 w = ((const float4*)qwk_s)[h*256 + e4];
      acc[h][0] += dot4(x0,w);
      acc[h][1] += dot4(x1,w);
      acc[h][2] += dot4(x2,w);
      acc[h][3] += dot4(x3,w);
    }
  }
#pragma unroll
  for (int h=0;h<NH;h++){
#pragma unroll
    for (int k=0;k<4;k++) acc[h][k] = warp_sum(acc[h][k]);
  }
  if (!lane){
#pragma unroll
    for (int h=0;h<NH;h++){
#pragma unroll
      for (int k=0;k<4;k++) g_p[((size_t)b*NH+h)*NS + s + k] = acc[h][k];
    }
  }
}

// K4: softmax over s for each (b,h) row, in place on g_p.
__global__ void k_softmax(){
  int row = blockIdx.x;                 // b*NH + h
  float* p = g_p + (size_t)row*NS;
  int t = threadIdx.x, lane = t & 31, wid = t >> 5;
  __shared__ float red[8];
  float v[8];
  float m = -3.4e38f;
#pragma unroll
  for (int i=0;i<8;i++){ v[i] = p[t + i*256]; m = fmaxf(m, v[i]); }
#pragma unroll
  for (int o=16;o>0;o>>=1) m = fmaxf(m, __shfl_xor_sync(0xffffffffu, m, o));
  if (!lane) red[wid] = m;
  __syncthreads();
  m = red[0];
#pragma unroll
  for (int i=1;i<8;i++) m = fmaxf(m, red[i]);
  float sum = 0.f;
#pragma unroll
  for (int i=0;i<8;i++){ v[i] = __expf(v[i]-m); sum += v[i]; }
  sum = warp_sum(sum);
  __syncthreads();
  if (!lane) red[wid] = sum;
  __syncthreads();
  float tot = red[0];
#pragma unroll
  for (int i=1;i<8;i++) tot += red[i];
  float inv = 1.f/tot;
#pragma unroll
  for (int i=0;i<8;i++) p[t + i*256] = v[i]*inv;
}

// K5: pv partials: g_pvp[b][sc][h][e] = sum_{s in chunk} p[b,h,s]*embV[b,s,e]
// Deterministic (no atomics). Block: 128 thr, owns 512 e (float4/thread).
__global__ void __launch_bounds__(128) k_pv(const float* __restrict__ embV){
  int ec = blockIdx.x, sc = blockIdx.y, b = blockIdx.z;
  __shared__ float ps[NH][SCLEN];
  int t = threadIdx.x;
  int s0 = sc*SCLEN;
#pragma unroll
  for (int i=0;i<8;i++){
    int idx = t + i*128;
    int h = idx >> 6, ss = idx & 63;
    ps[h][ss] = g_p[((size_t)b*NH+h)*NS + s0 + ss];
  }
  __syncthreads();
  int e4 = ec*128 + t;
  const float4* v = (const float4*)(embV + ((size_t)b*NS + s0)*NE) + e4;
  float4 acc[NH];
#pragma unroll
  for (int h=0;h<NH;h++) acc[h] = make_float4(0.f,0.f,0.f,0.f);
#pragma unroll 4
  for (int ss=0; ss<SCLEN; ++ss){
    float4 x = v[(size_t)ss*256];
#pragma unroll
    for (int h=0;h<NH;h++){
      float pw = ps[h][ss];
      acc[h].x = fmaf(pw,x.x,acc[h].x);
      acc[h].y = fmaf(pw,x.y,acc[h].y);
      acc[h].z = fmaf(pw,x.z,acc[h].z);
      acc[h].w = fmaf(pw,x.w,acc[h].w);
    }
  }
  float4* outp = (float4*)g_pvp + ((size_t)(b*SC + sc)*NH)*256 + e4;
#pragma unroll
  for (int h=0;h<NH;h++) outp[h*256] = acc[h];
}

// K6: reduce partials over SC chunks
__global__ void k_pvred(){
  int i4 = blockIdx.x*256 + threadIdx.x;   // 0..8191 over NB*NH*NE/4
  int b = i4 >> 12;                         // NH*NE/4 = 4096
  int r = i4 & 4095;
  const float4* src = (const float4*)g_pvp + (size_t)b*SC*4096 + r;
  float4 acc = make_float4(0.f,0.f,0.f,0.f);
#pragma unroll
  for (int c=0;c<SC;c++){
    float4 x = src[(size_t)c*4096];
    acc.x+=x.x; acc.y+=x.y; acc.z+=x.z; acc.w+=x.w;
  }
  ((float4*)g_pv)[i4] = acc;
}

// K7: g_o[b][i] = dot(g_pv[b][i>>6][:], Wv[i][:])   (warp per output)
__global__ void k_o(const float* __restrict__ Wv){
  int gw = (blockIdx.x*blockDim.x + threadIdx.x) >> 5;
  int lane = threadIdx.x & 31;
  int b = gw >> 10, i = gw & 1023;
  int h = i >> 6;
  const float4* xr = (const float4*)(g_pv + ((size_t)b*NH + h)*NE);
  const float4* wr = (const float4*)(Wv + (size_t)i*NE);
  float acc = 0.f;
#pragma unroll
  for (int it=0; it<8; ++it) acc += dot4(xr[lane+it*32], wr[lane+it*32]);
  acc = warp_sum(acc);
  if (!lane) g_o[b*NE+i] = acc;
}

// K8: g_y[b][j] = dot(g_o[b][:], Wo[j][:])   (warp per output)
__global__ void k_y(const float* __restrict__ Wo){
  int gw = (blockIdx.x*blockDim.x + threadIdx.x) >> 5;
  int lane = threadIdx.x & 31;
  int b = gw >> 10, j = gw & 1023;
  const float4* xr = (const float4*)(g_o + (size_t)b*NE);
  const float4* wr = (const float4*)(Wo + (size_t)j*NE);
  float acc = 0.f;
#pragma unroll
  for (int it=0; it<8; ++it) acc += dot4(xr[lane+it*32], wr[lane+it*32]);
  acc = warp_sum(acc);
  if (!lane) g_y[b*NE+j] = acc;
}

// K9: broadcast y row to all S positions (store-bound, 32 MB)
__global__ void k_bcast(float* __restrict__ out){
  int gi = blockIdx.x*blockDim.x + threadIdx.x;  // float4 idx over NB*NS*NE/4
  int e4 = gi & 255;
  int bs = gi >> 8;
  int b  = bs >> 11;                              // / NS
  float4 y = ((const float4*)g_y)[b*256 + e4];
  ((float4*)out)[gi] = y;
}

extern "C" void kernel_launch(void* const* d_in, const int* in_sizes, int n_in,
                              void* d_out, int out_size){
  const float* inputs = (const float*)d_in[0];
  const float* embV   = (const float*)d_in[1];
  const float* embK   = (const float*)d_in[2];
  const float* Wq     = (const float*)d_in[3];
  const float* Wk     = (const float*)d_in[4];
  const float* Wv     = (const float*)d_in[5];
  const float* Wo     = (const float*)d_in[6];
  float* out = (float*)d_out;

  cudaFuncSetAttribute(k_scores, cudaFuncAttributeMaxDynamicSharedMemorySize, 65536);

  k_q      <<<256, 256>>>(inputs, Wq);
  k_qwk    <<<dim3(NH, NB), 256>>>(Wk);
  k_scores <<<dim3(NS/32, NB), 256, 65536>>>(embK);
  k_softmax<<<NB*NH, 256>>>();
  k_pv     <<<dim3(2, SC, NB), 128>>>(embV);
  k_pvred  <<<32, 256>>>();
  k_o      <<<256, 256>>>(Wv);
  k_y      <<<256, 256>>>(Wo);
  k_bcast  <<<(NB*NS*NE/4)/256, 256>>>(out);
}

// round 2
// speedup vs baseline: 1.1393x; 1.1393x over previous
#include <cuda_runtime.h>

#define NB 2
#define NS 2048
#define NE 1024
#define NH 16
#define ND 64
#define SC 32       // s-chunks for pv partials
#define SCLEN 64    // s per chunk (SC*SCLEN == NS)

// Scratch (allocation-free: device globals)
__device__ float g_qwk[NB*NH*NE];        // [b][h][e]
__device__ float g_p[NB*NH*NS];          // raw scores
__device__ float g_pvp[NB*SC*NH*NE];     // unnormalized pv partials [b][sc][h][e]
__device__ float g_sump[NB*SC*NH];       // per-chunk exp sums
__device__ float g_pv[NB*NH*NE];
__device__ float g_o[NB*NE];
__device__ float g_y[NB*NE];

__device__ __forceinline__ float dot4(float4 a, float4 b){
  return fmaf(a.x,b.x, fmaf(a.y,b.y, fmaf(a.z,b.z, a.w*b.w)));
}
__device__ __forceinline__ float warp_sum(float v){
#pragma unroll
  for (int o=16;o>0;o>>=1) v += __shfl_xor_sync(0xffffffffu, v, o);
  return v;
}

// K1: fused q + qwk.  Block (h, b), 512 threads.
// Phase 1: q[d] = dot(inputs[b,S-1,:], Wq[h*64+d,:])  (warp w -> d = 4w..4w+3)
// Phase 2: qwk[b][h][e] = sum_d q[d] * Wk[h*64+d][e]
__global__ void __launch_bounds__(512) k_qk(const float* __restrict__ inputs,
                                            const float* __restrict__ Wq,
                                            const float* __restrict__ Wk){
  int h = blockIdx.x, b = blockIdx.y;
  __shared__ float qs[ND];
  __shared__ float4 buf[2][256];
  int tid = threadIdx.x, lane = tid & 31, w = tid >> 5;
  const float4* xr = (const float4*)(inputs + ((size_t)b*NS + (NS-1))*NE);
  float acc[4] = {0.f,0.f,0.f,0.f};
  int dbase = w*4;
#pragma unroll
  for (int it=0; it<8; ++it){
    int e4 = lane + it*32;
    float4 x = xr[e4];
#pragma unroll
    for (int k=0;k<4;k++){
      const float4* wr = (const float4*)(Wq + (size_t)(h*ND + dbase + k)*NE);
      acc[k] += dot4(x, wr[e4]);
    }
  }
#pragma unroll
  for (int k=0;k<4;k++){
    float s = warp_sum(acc[k]);
    if (!lane) qs[dbase+k] = s;
  }
  __syncthreads();
  // Phase 2
  int e4 = tid & 255;
  int dh = tid >> 8;                 // 0 or 1
  const float4* Wk4 = (const float4*)Wk;
  float4 a = make_float4(0.f,0.f,0.f,0.f);
#pragma unroll 8
  for (int dd=0; dd<32; ++dd){
    int d = dh*32 + dd;
    float qv = qs[d];
    float4 wv = Wk4[(size_t)(h*ND + d)*256 + e4];
    a.x = fmaf(qv,wv.x,a.x); a.y = fmaf(qv,wv.y,a.y);
    a.z = fmaf(qv,wv.z,a.z); a.w = fmaf(qv,wv.w,a.w);
  }
  buf[dh][e4] = a;
  __syncthreads();
  if (tid < 256){
    float4 p0 = buf[0][tid], p1 = buf[1][tid];
    float4 r = make_float4(p0.x+p1.x, p0.y+p1.y, p0.z+p1.z, p0.w+p1.w);
    ((float4*)g_qwk)[(size_t)(b*NH + h)*256 + tid] = r;
  }
}

// K2: raw scores[b][h][s] = dot(embK[b,s,:], qwk[b,h,:]); qwk cached in 64KB smem.
__global__ void __launch_bounds__(256) k_scores(const float* __restrict__ embK){
  extern __shared__ float qwk_s[];     // [NH][NE] = 64 KB
  int b = blockIdx.y;
  {
    const float4* src = (const float4*)(g_qwk + (size_t)b*NH*NE);
    float4* dst = (float4*)qwk_s;
#pragma unroll
    for (int i=0;i<16;i++) dst[threadIdx.x + i*256] = src[threadIdx.x + i*256];
  }
  __syncthreads();
  int wid = threadIdx.x >> 5, lane = threadIdx.x & 31;
  int s = blockIdx.x*32 + wid*4;
  const float4* r = (const float4*)(embK + ((size_t)b*NS + s)*NE);
  float acc[NH][4];
#pragma unroll
  for (int h=0;h<NH;h++){
#pragma unroll
    for (int k=0;k<4;k++) acc[h][k]=0.f;
  }
#pragma unroll
  for (int it=0; it<8; ++it){
    int e4 = lane + it*32;
    float4 x0 = r[e4];
    float4 x1 = r[e4 + 256];
    float4 x2 = r[e4 + 512];
    float4 x3 = r[e4 + 768];
#pragma unroll
    for (int h=0; h<NH; ++h){
      float4 w = ((const float4*)qwk_s)[h*256 + e4];
      acc[h][0] += dot4(x0,w);
      acc[h][1] += dot4(x1,w);
      acc[h][2] += dot4(x2,w);
      acc[h][3] += dot4(x3,w);
    }
  }
#pragma unroll
  for (int h=0;h<NH;h++){
#pragma unroll
    for (int k=0;k<4;k++) acc[h][k] = warp_sum(acc[h][k]);
  }
  if (!lane){
#pragma unroll
    for (int h=0;h<NH;h++){
#pragma unroll
      for (int k=0;k<4;k++) g_p[((size_t)b*NH+h)*NS + s + k] = acc[h][k];
    }
  }
}

// K3: unnormalized pv partials with on-the-fly exp (no softmax pass):
//   g_pvp[b][sc][h][e] = sum_{s in chunk} exp(score[b,h,s]) * embV[b,s,e]
//   g_sump[b][sc][h]   = sum_{s in chunk} exp(score[b,h,s])
// Block: 256 thr = 2 head-groups x 128 e-threads. Grid (2 e-chunks, SC, NB).
__global__ void __launch_bounds__(256) k_pv(const float* __restrict__ embV){
  int ec = blockIdx.x, sc = blockIdx.y, b = blockIdx.z;
  __shared__ float ps[NH][SCLEN];
  int tid = threadIdx.x;
  int s0 = sc*SCLEN;
  // load raw scores, exponentiate
#pragma unroll
  for (int i=0;i<4;i++){
    int idx = tid + i*256;                // 0..1023
    int h = idx >> 6, ss = idx & 63;
    ps[h][ss] = __expf(g_p[((size_t)b*NH+h)*NS + s0 + ss]);
  }
  __syncthreads();
  // per-chunk exp sums (only e-chunk 0 writes)
  if (ec == 0 && tid < NH){
    float su = 0.f;
#pragma unroll
    for (int ss=0; ss<SCLEN; ++ss) su += ps[tid][ss];
    g_sump[((size_t)b*SC + sc)*NH + tid] = su;
  }
  int hg = tid >> 7;                      // head group 0/1
  int t  = tid & 127;
  int e4 = ec*128 + t;
  const float4* v = (const float4*)(embV + ((size_t)b*NS + s0)*NE) + e4;
  float4 acc[8];
#pragma unroll
  for (int h8=0;h8<8;h8++) acc[h8] = make_float4(0.f,0.f,0.f,0.f);
#pragma unroll 4
  for (int ss=0; ss<SCLEN; ++ss){
    float4 x = v[(size_t)ss*256];
#pragma unroll
    for (int h8=0;h8<8;h8++){
      float pw = ps[hg*8 + h8][ss];
      acc[h8].x = fmaf(pw,x.x,acc[h8].x);
      acc[h8].y = fmaf(pw,x.y,acc[h8].y);
      acc[h8].z = fmaf(pw,x.z,acc[h8].z);
      acc[h8].w = fmaf(pw,x.w,acc[h8].w);
    }
  }
  float4* outp = (float4*)g_pvp + ((size_t)(b*SC + sc)*NH)*256 + e4;
#pragma unroll
  for (int h8=0;h8<8;h8++) outp[(hg*8 + h8)*256] = acc[h8];
}

// K4: reduce pv partials over SC chunks
__global__ void k_pvred(){
  int i4 = blockIdx.x*256 + threadIdx.x;   // over NB*NH*NE/4 = 8192
  int b = i4 >> 12;
  int r = i4 & 4095;
  const float4* src = (const float4*)g_pvp + (size_t)b*SC*4096 + r;
  float4 acc = make_float4(0.f,0.f,0.f,0.f);
#pragma unroll
  for (int c=0;c<SC;c++){
    float4 x = src[(size_t)c*4096];
    acc.x+=x.x; acc.y+=x.y; acc.z+=x.z; acc.w+=x.w;
  }
  ((float4*)g_pv)[i4] = acc;
}

// K5: g_o[b][i] = dot(g_pv[b][h_i][:], Wv[i][:]) / rowsum[b][h_i]
__global__ void k_o(const float* __restrict__ Wv){
  int gw = (blockIdx.x*blockDim.x + threadIdx.x) >> 5;
  int lane = threadIdx.x & 31;
  int b = gw >> 10, i = gw & 1023;
  int h = i >> 6;
  // row exp-sum: each lane loads one chunk's partial sum (SC == 32)
  float ssum = warp_sum(g_sump[((size_t)b*SC + lane)*NH + h]);
  const float4* xr = (const float4*)(g_pv + ((size_t)b*NH + h)*NE);
  const float4* wr = (const float4*)(Wv + (size_t)i*NE);
  float acc = 0.f;
#pragma unroll
  for (int it=0; it<8; ++it) acc += dot4(xr[lane+it*32], wr[lane+it*32]);
  acc = warp_sum(acc);
  if (!lane) g_o[b*NE+i] = acc / ssum;
}

// K6: g_y[b][j] = dot(g_o[b][:], Wo[j][:])
__global__ void k_y(const float* __restrict__ Wo){
  int gw = (blockIdx.x*blockDim.x + threadIdx.x) >> 5;
  int lane = threadIdx.x & 31;
  int b = gw >> 10, j = gw & 1023;
  const float4* xr = (const float4*)(g_o + (size_t)b*NE);
  const float4* wr = (const float4*)(Wo + (size_t)j*NE);
  float acc = 0.f;
#pragma unroll
  for (int it=0; it<8; ++it) acc += dot4(xr[lane+it*32], wr[lane+it*32]);
  acc = warp_sum(acc);
  if (!lane) g_y[b*NE+j] = acc;
}

// K7: broadcast y row to all S positions
__global__ void k_bcast(float* __restrict__ out){
  int gi = blockIdx.x*blockDim.x + threadIdx.x;  // float4 idx over NB*NS*NE/4
  int e4 = gi & 255;
  int b  = gi >> 19;                              // / (NS*NE/4)
  float4 y = ((const float4*)g_y)[b*256 + e4];
  ((float4*)out)[gi] = y;
}

extern "C" void kernel_launch(void* const* d_in, const int* in_sizes, int n_in,
                              void* d_out, int out_size){
  const float* inputs = (const float*)d_in[0];
  const float* embV   = (const float*)d_in[1];
  const float* embK   = (const float*)d_in[2];
  const float* Wq     = (const float*)d_in[3];
  const float* Wk     = (const float*)d_in[4];
  const float* Wv     = (const float*)d_in[5];
  const float* Wo     = (const float*)d_in[6];
  float* out = (float*)d_out;

  cudaFuncSetAttribute(k_scores, cudaFuncAttributeMaxDynamicSharedMemorySize, 65536);

  k_qk     <<<dim3(NH, NB), 512>>>(inputs, Wq, Wk);
  k_scores <<<dim3(NS/32, NB), 256, 65536>>>(embK);
  k_pv     <<<dim3(2, SC, NB), 256>>>(embV);
  k_pvred  <<<32, 256>>>();
  k_o      <<<256, 256>>>(Wv);
  k_y      <<<256, 256>>>(Wo);
  k_bcast  <<<(NB*NS*NE/4)/256, 256>>>(out);
}